// round 1
// baseline (speedup 1.0000x reference)
#include <cuda_runtime.h>
#include <cuda_bf16.h>
#include <math.h>

// Problem constants
#define BATCH 4
#define SEQ   4096
#define CDIM  1024
#define HEADS 16
#define HDIM  64
#define MROWS (BATCH * SEQ)         // 16384
#define QKVN  (3 * CDIM)            // 3072

// Scratch (allowed: __device__ globals, no runtime alloc)
__device__ float g_q[MROWS * CDIM];     // [B,H,N,D]
__device__ float g_k[MROWS * CDIM];     // [B,H,N,D]
__device__ float g_v[MROWS * CDIM];     // [B,H,N,D]
__device__ float g_ctx[BATCH * HEADS * HDIM * HDIM];  // [BH,64,64]
__device__ float g_attn[MROWS * CDIM];  // [B,N,C]

// ---------------------------------------------------------------------------
// SGEMM: C[M,N] = A[M,K] @ B[K,N] + bias[N]
// MODE 0: plain write to Cout
// MODE 1: scatter into g_q/g_k/g_v as [B,H,N,D]
// BM=BN=128, BK=16, 256 threads, 8x8 per-thread tile.
// ---------------------------------------------------------------------------
template<int MODE>
__global__ void __launch_bounds__(256)
sgemm_kernel(const float* __restrict__ A, const float* __restrict__ B,
             const float* __restrict__ bias, float* __restrict__ Cout,
             int M, int N, int K)
{
    const int BM = 128, BN = 128, BK = 16;
    __shared__ float As[BK][BM];       // transposed A tile
    __shared__ float Bs[BK][BN];

    const int tid = threadIdx.x;
    const int tx = tid & 15;           // 0..15 (col group)
    const int ty = tid >> 4;           // 0..15 (row group)
    const int bm = blockIdx.y * BM;
    const int bn = blockIdx.x * BN;

    float acc[8][8];
#pragma unroll
    for (int i = 0; i < 8; i++)
#pragma unroll
        for (int j = 0; j < 8; j++) acc[i][j] = 0.f;

    for (int kt = 0; kt < K; kt += BK) {
        // Load A tile: 128 rows x 16 cols = 512 float4 / 256 threads = 2 each
#pragma unroll
        for (int l = 0; l < 2; l++) {
            int idx = tid + l * 256;
            int row = idx >> 2;        // 0..127
            int c4  = idx & 3;         // 0..3
            const float4 va = *reinterpret_cast<const float4*>(
                &A[(size_t)(bm + row) * K + kt + c4 * 4]);
            As[c4 * 4 + 0][row] = va.x;
            As[c4 * 4 + 1][row] = va.y;
            As[c4 * 4 + 2][row] = va.z;
            As[c4 * 4 + 3][row] = va.w;
        }
        // Load B tile: 16 rows x 128 cols = 512 float4 / 256 threads = 2 each
#pragma unroll
        for (int l = 0; l < 2; l++) {
            int idx = tid + l * 256;
            int krow = idx >> 5;       // 0..15
            int c4   = idx & 31;       // 0..31
            const float4 vb = *reinterpret_cast<const float4*>(
                &B[(size_t)(kt + krow) * N + bn + c4 * 4]);
            *reinterpret_cast<float4*>(&Bs[krow][c4 * 4]) = vb;
        }
        __syncthreads();

#pragma unroll
        for (int kk = 0; kk < BK; kk++) {
            float af[8], bf[8];
#pragma unroll
            for (int i = 0; i < 8; i++) af[i] = As[kk][ty * 8 + i];
#pragma unroll
            for (int j = 0; j < 8; j++) bf[j] = Bs[kk][tx * 8 + j];
#pragma unroll
            for (int i = 0; i < 8; i++)
#pragma unroll
                for (int j = 0; j < 8; j++)
                    acc[i][j] = fmaf(af[i], bf[j], acc[i][j]);
        }
        __syncthreads();
    }

    // Epilogue
#pragma unroll
    for (int i = 0; i < 8; i++) {
        int m = bm + ty * 8 + i;
        int b = m >> 12;               // m / 4096
        int n = m & 4095;
#pragma unroll
        for (int j = 0; j < 8; j++) {
            int col = bn + tx * 8 + j;
            float val = acc[i][j] + bias[col];
            if (MODE == 0) {
                Cout[(size_t)m * N + col] = val;
            } else {
                int s   = col >> 10;        // 0,1,2 (q/k/v)
                int rem = col & 1023;
                int h   = rem >> 6;
                int dd  = rem & 63;
                size_t off = (((size_t)(b * HEADS + h) * SEQ + n) << 6) + dd;
                float* dst = (s == 0) ? g_q : (s == 1) ? g_k : g_v;
                dst[off] = val;
            }
        }
    }
}

// ---------------------------------------------------------------------------
// Fused: column-softmax of K over N, then context[d,e] = sum_n softk[n,d]*v[n,e]
// One block per (b,h). 512 threads.
// ---------------------------------------------------------------------------
__global__ void __launch_bounds__(512)
kv_context_kernel(const float* __restrict__ Kp, const float* __restrict__ Vp,
                  float* __restrict__ Ctx)
{
    const int bh = blockIdx.x;   // 0..63
    const float* kp = Kp + (size_t)bh * SEQ * HDIM;
    const float* vp = Vp + (size_t)bh * SEQ * HDIM;

    __shared__ float colmax[HDIM];
    __shared__ float colsum[HDIM];
    __shared__ float red[512];
    const int TN = 32;
    __shared__ float kt[TN][HDIM + 1];
    __shared__ float vt[TN][HDIM + 1];

    const int tid = threadIdx.x;
    const int d = tid & 63, g = tid >> 6;     // g in 0..7

    // Phase 1a: column max over N
    float m = -1e30f;
    for (int n = g; n < SEQ; n += 8)
        m = fmaxf(m, kp[n * HDIM + d]);
    red[tid] = m;
    __syncthreads();
    if (g == 0) {
        float mm = red[d];
#pragma unroll
        for (int j = 1; j < 8; j++) mm = fmaxf(mm, red[j * 64 + d]);
        colmax[d] = mm;
    }
    __syncthreads();

    // Phase 1b: column sum of exp
    float s = 0.f;
    float cm = colmax[d];
    for (int n = g; n < SEQ; n += 8)
        s += __expf(kp[n * HDIM + d] - cm);
    red[tid] = s;
    __syncthreads();
    if (g == 0) {
        float ss = red[d];
#pragma unroll
        for (int j = 1; j < 8; j++) ss += red[j * 64 + d];
        colsum[d] = ss;
    }

    // Phase 2: context accumulation. Thread owns (e = tid&63, d = dg*8+j)
    const int e = tid & 63;
    const int dg = tid >> 6;     // 0..7
    float acc[8];
#pragma unroll
    for (int j = 0; j < 8; j++) acc[j] = 0.f;

    for (int n0 = 0; n0 < SEQ; n0 += TN) {
        __syncthreads();
        for (int i = tid; i < TN * HDIM; i += 512) {
            int r = i >> 6, c = i & 63;
            kt[r][c] = __expf(kp[(n0 + r) * HDIM + c] - colmax[c]);
            vt[r][c] = vp[(n0 + r) * HDIM + c];
        }
        __syncthreads();
#pragma unroll 4
        for (int r = 0; r < TN; r++) {
            float vv = vt[r][e];
#pragma unroll
            for (int j = 0; j < 8; j++)
                acc[j] = fmaf(kt[r][dg * 8 + j], vv, acc[j]);
        }
    }
    __syncthreads();

#pragma unroll
    for (int j = 0; j < 8; j++) {
        int dd = dg * 8 + j;
        Ctx[(size_t)bh * HDIM * HDIM + dd * HDIM + e] = acc[j] / colsum[dd];
    }
}

// ---------------------------------------------------------------------------
// Fused: row-softmax of Q over D, then out[n,e] = sum_d p[d]*ctx[d,e],
// written transposed into [B,N,C].
// Grid: (SEQ/8, BH). 256 threads = 8 warps, one warp per row.
// ---------------------------------------------------------------------------
__global__ void __launch_bounds__(256)
q_attend_kernel(const float* __restrict__ Qp, const float* __restrict__ Ctx,
                float* __restrict__ Attn)
{
    const int bh = blockIdx.y;
    const int b = bh >> 4, h = bh & 15;
    __shared__ float ctx[HDIM][HDIM + 1];
    __shared__ float pbuf[8][HDIM];

    for (int i = threadIdx.x; i < HDIM * HDIM; i += 256)
        ctx[i >> 6][i & 63] = Ctx[(size_t)bh * HDIM * HDIM + i];
    __syncthreads();

    const int warp = threadIdx.x >> 5, lane = threadIdx.x & 31;
    const int n = blockIdx.x * 8 + warp;
    const float* qrow = Qp + ((size_t)bh * SEQ + n) * HDIM;

    float q0 = qrow[lane], q1 = qrow[lane + 32];
    float m = fmaxf(q0, q1);
#pragma unroll
    for (int off = 16; off; off >>= 1)
        m = fmaxf(m, __shfl_xor_sync(0xffffffffu, m, off));
    float e0 = __expf(q0 - m), e1 = __expf(q1 - m);
    float s = e0 + e1;
#pragma unroll
    for (int off = 16; off; off >>= 1)
        s += __shfl_xor_sync(0xffffffffu, s, off);
    float inv = 1.f / s;
    pbuf[warp][lane] = e0 * inv;
    pbuf[warp][lane + 32] = e1 * inv;
    __syncwarp();

    float acc0 = 0.f, acc1 = 0.f;
#pragma unroll
    for (int d2 = 0; d2 < HDIM; d2++) {
        float p = pbuf[warp][d2];
        acc0 = fmaf(p, ctx[d2][lane], acc0);
        acc1 = fmaf(p, ctx[d2][lane + 32], acc1);
    }
    float* o = Attn + ((size_t)(b * SEQ + n)) * CDIM + h * HDIM;
    o[lane] = acc0;
    o[lane + 32] = acc1;
}

// ---------------------------------------------------------------------------
extern "C" void kernel_launch(void* const* d_in, const int* in_sizes, int n_in,
                              void* d_out, int out_size)
{
    const float* x      = (const float*)d_in[0];
    const float* W_qkv  = (const float*)d_in[1];
    const float* b_qkv  = (const float*)d_in[2];
    const float* W_proj = (const float*)d_in[3];
    const float* b_proj = (const float*)d_in[4];
    float* out = (float*)d_out;

    float *q, *k, *v, *ctx, *attn;
    cudaGetSymbolAddress((void**)&q,    g_q);
    cudaGetSymbolAddress((void**)&k,    g_k);
    cudaGetSymbolAddress((void**)&v,    g_v);
    cudaGetSymbolAddress((void**)&ctx,  g_ctx);
    cudaGetSymbolAddress((void**)&attn, g_attn);

    // 1) qkv = x @ W_qkv + b_qkv, scattered to q/k/v [B,H,N,D]
    {
        dim3 grid(QKVN / 128, MROWS / 128);
        sgemm_kernel<1><<<grid, 256>>>(x, W_qkv, b_qkv, nullptr,
                                       MROWS, QKVN, CDIM);
    }
    // 2) softmax_N(k)^T @ v -> ctx [BH,64,64]
    kv_context_kernel<<<BATCH * HEADS, 512>>>(k, v, ctx);
    // 3) softmax_D(q) @ ctx -> attn [B,N,C]
    {
        dim3 grid(SEQ / 8, BATCH * HEADS);
        q_attend_kernel<<<grid, 256>>>(q, ctx, attn);
    }
    // 4) out = attn @ W_proj + b_proj
    {
        dim3 grid(CDIM / 128, MROWS / 128);
        sgemm_kernel<0><<<grid, 256>>>(attn, W_proj, b_proj, out,
                                       MROWS, CDIM, CDIM);
    }
}

// round 3
// speedup vs baseline: 1.5877x; 1.5877x over previous
#include <cuda_runtime.h>
#include <cuda_bf16.h>
#include <cstdint>
#include <math.h>

#define BATCH 4
#define SEQ   4096
#define CDIM  1024
#define HEADS 16
#define HDIM  64
#define MROWS 16384
#define K3    3072          // 3*CDIM : split-concatenated K
#define BH    64            // BATCH*HEADS

// ---------------- scratch (device globals; no runtime alloc) ----------------
__device__ __nv_bfloat16 g_A[(size_t)MROWS * K3];   // A' [M x 3K]
__device__ __nv_bfloat16 g_Bq[(size_t)K3 * K3];     // W_qkv' [3072 N x 3072 K'] K-major
__device__ __nv_bfloat16 g_Bp[(size_t)CDIM * K3];   // W_proj' [1024 N x 3072 K']
__device__ float g_q[(size_t)MROWS * CDIM];         // [BH][N][D]
__device__ float g_k[(size_t)MROWS * CDIM];
__device__ float g_v[(size_t)MROWS * CDIM];
__device__ float g_ctx[BH * HDIM * HDIM];
__device__ float g_colsum[BH * HDIM];

__device__ __forceinline__ uint32_t smem_u32(const void* p) {
    uint32_t a;
    asm("{ .reg .u64 t; cvta.to.shared.u64 t, %1; cvt.u32.u64 %0, t; }" : "=r"(a) : "l"(p));
    return a;
}
__device__ __forceinline__ void cpa16(uint32_t saddr, const void* g) {
    asm volatile("cp.async.cg.shared.global [%0], [%1], 16;" :: "r"(saddr), "l"(g));
}
#define CPA_COMMIT() asm volatile("cp.async.commit_group;" ::: "memory")

__device__ __forceinline__ void ldm_x4(uint32_t* f, uint32_t addr) {
    asm volatile("ldmatrix.sync.aligned.m8n8.x4.shared.b16 {%0,%1,%2,%3}, [%4];"
        : "=r"(f[0]), "=r"(f[1]), "=r"(f[2]), "=r"(f[3]) : "r"(addr));
}
__device__ __forceinline__ void mma_bf16(float* d, const uint32_t* a, uint32_t b0, uint32_t b1) {
    asm volatile("mma.sync.aligned.m16n8k16.row.col.f32.bf16.bf16.f32 "
        "{%0,%1,%2,%3}, {%4,%5,%6,%7}, {%8,%9}, {%0,%1,%2,%3};"
        : "+f"(d[0]), "+f"(d[1]), "+f"(d[2]), "+f"(d[3])
        : "r"(a[0]), "r"(a[1]), "r"(a[2]), "r"(a[3]), "r"(b0), "r"(b1));
}

// ---------------- HMMA GEMM: C[M,Nn] = A'[M,K3] x B'[Nn,K3]^T + bias ----------------
// BM=BN=128, BK=32, 256 thr, warp tile 64x32. Smem rows strided 40 elems (80B).
#define BK      32
#define SROW    40            // elements per smem row (80B, conflict-free)
#define NKIT    (K3 / BK)     // 96

template<int MODE>
__global__ void __launch_bounds__(256)
gemm_hmma(const __nv_bfloat16* __restrict__ A, const __nv_bfloat16* __restrict__ Bm,
          const float* __restrict__ bias, float* __restrict__ Cout, int Nn)
{
    __shared__ __nv_bfloat16 sA[2][128 * SROW];
    __shared__ __nv_bfloat16 sB[2][128 * SROW];

    const int tid = threadIdx.x, wid = tid >> 5, lane = tid & 31;
    const int bm = blockIdx.y * 128, bn = blockIdx.x * 128;
    const int mbase = (wid >> 2) * 64, nbase = (wid & 3) * 32;

    const uint32_t sa0 = smem_u32(&sA[0][0]);
    const uint32_t sb0 = smem_u32(&sB[0][0]);
    const uint32_t stg = (uint32_t)(128 * SROW * 2);   // bytes per stage

    // cp.async staging indices (4 16B-chunks per 64B row)
    const int ldrow = tid >> 2, ldpos = tid & 3;

    float acc[4][4][4];
#pragma unroll
    for (int i = 0; i < 4; i++)
#pragma unroll
        for (int j = 0; j < 4; j++)
#pragma unroll
            for (int r = 0; r < 4; r++) acc[i][j][r] = 0.f;

    // ldmatrix lane addressing (element offsets within tile)
    const int a_row = lane & 15, a_kof = (lane >> 4) * 8;
    const int b_row = (lane & 7) + ((lane >> 4) & 1) * 8;
    const int b_kof = ((lane >> 3) & 1) * 8;

    // prologue load of tile 0
    {
#pragma unroll
        for (int l = 0; l < 2; l++) {
            int row = ldrow + l * 64;
            cpa16(sa0 + (uint32_t)(row * SROW + ldpos * 8) * 2,
                  A + (size_t)(bm + row) * K3 + ldpos * 8);
            cpa16(sb0 + (uint32_t)(row * SROW + ldpos * 8) * 2,
                  Bm + (size_t)(bn + row) * K3 + ldpos * 8);
        }
        CPA_COMMIT();
    }

    for (int i = 0; i < NKIT; i++) {
        const int buf = i & 1;
        if (i + 1 < NKIT) {
            const uint32_t off = (uint32_t)((buf ^ 1) * stg);
            const int kt = (i + 1) * BK;
#pragma unroll
            for (int l = 0; l < 2; l++) {
                int row = ldrow + l * 64;
                cpa16(sa0 + off + (uint32_t)(row * SROW + ldpos * 8) * 2,
                      A + (size_t)(bm + row) * K3 + kt + ldpos * 8);
                cpa16(sb0 + off + (uint32_t)(row * SROW + ldpos * 8) * 2,
                      Bm + (size_t)(bn + row) * K3 + kt + ldpos * 8);
            }
            CPA_COMMIT();
            asm volatile("cp.async.wait_group 1;" ::: "memory");
        } else {
            asm volatile("cp.async.wait_group 0;" ::: "memory");
        }
        __syncthreads();

        const uint32_t sa = sa0 + buf * stg;
        const uint32_t sbB = sb0 + buf * stg;
#pragma unroll
        for (int kc = 0; kc < 2; kc++) {
            uint32_t af[4][4], bfm[2][4];
#pragma unroll
            for (int mt = 0; mt < 4; mt++)
                ldm_x4(af[mt], sa + (uint32_t)((mbase + mt * 16 + a_row) * SROW
                                               + kc * 16 + a_kof) * 2);
#pragma unroll
            for (int np = 0; np < 2; np++)
                ldm_x4(bfm[np], sbB + (uint32_t)((nbase + np * 16 + b_row) * SROW
                                                 + kc * 16 + b_kof) * 2);
#pragma unroll
            for (int mt = 0; mt < 4; mt++)
#pragma unroll
                for (int nt = 0; nt < 4; nt++)
                    mma_bf16(acc[mt][nt], af[mt],
                             bfm[nt >> 1][(nt & 1) * 2], bfm[nt >> 1][(nt & 1) * 2 + 1]);
        }
        __syncthreads();
    }

    // epilogue: direct float2 stores
    const int r0 = lane >> 2, cpair = (lane & 3) * 2;
#pragma unroll
    for (int mt = 0; mt < 4; mt++) {
#pragma unroll
        for (int nt = 0; nt < 4; nt++) {
            int col = bn + nbase + nt * 8 + cpair;
            float bv0 = bias[col], bv1 = bias[col + 1];
            int m0 = bm + mbase + mt * 16 + r0;
            float2 v0 = make_float2(acc[mt][nt][0] + bv0, acc[mt][nt][1] + bv1);
            float2 v1 = make_float2(acc[mt][nt][2] + bv0, acc[mt][nt][3] + bv1);
            if (MODE == 0) {
                *(float2*)&Cout[(size_t)m0 * Nn + col] = v0;
                *(float2*)&Cout[(size_t)(m0 + 8) * Nn + col] = v1;
            } else {
                int s = col >> 10, rem = col & 1023;
                int h = rem >> 6, dd = rem & 63;
                float* dst = (s == 0) ? g_q : (s == 1) ? g_k : g_v;
                {
                    int b = m0 >> 12, n = m0 & 4095;
                    *(float2*)&dst[(((size_t)(b * HEADS + h) * SEQ + n) << 6) + dd] = v0;
                }
                {
                    int m1 = m0 + 8, b = m1 >> 12, n = m1 & 4095;
                    *(float2*)&dst[(((size_t)(b * HEADS + h) * SEQ + n) << 6) + dd] = v1;
                }
            }
        }
    }
}

// ---------------- split-conversion kernels ----------------
// x [M x 1024] fp32 -> g_A [M x 3072] bf16 = [hi | hi | lo]
__global__ void __launch_bounds__(256) convA(const float* __restrict__ X) {
    int i = blockIdx.x * 256 + threadIdx.x;          // quad index
    int m = i >> 8;
    int k = (i & 255) << 2;
    float4 v = *(const float4*)(X + (size_t)m * CDIM + k);
    __nv_bfloat16 h0 = __float2bfloat16(v.x), h1 = __float2bfloat16(v.y);
    __nv_bfloat16 h2 = __float2bfloat16(v.z), h3 = __float2bfloat16(v.w);
    __nv_bfloat16 l0 = __float2bfloat16(v.x - __bfloat162float(h0));
    __nv_bfloat16 l1 = __float2bfloat16(v.y - __bfloat162float(h1));
    __nv_bfloat16 l2 = __float2bfloat16(v.z - __bfloat162float(h2));
    __nv_bfloat16 l3 = __float2bfloat16(v.w - __bfloat162float(h3));
    __nv_bfloat16* b = g_A + (size_t)m * K3 + k;
    __nv_bfloat162 H01; H01.x = h0; H01.y = h1;
    __nv_bfloat162 H23; H23.x = h2; H23.y = h3;
    __nv_bfloat162 L01; L01.x = l0; L01.y = l1;
    __nv_bfloat162 L23; L23.x = l2; L23.y = l3;
    ((__nv_bfloat162*)b)[0] = H01;              ((__nv_bfloat162*)b)[1] = H23;
    ((__nv_bfloat162*)(b + 1024))[0] = H01;     ((__nv_bfloat162*)(b + 1024))[1] = H23;
    ((__nv_bfloat162*)(b + 2048))[0] = L01;     ((__nv_bfloat162*)(b + 2048))[1] = L23;
}

// W [1024 K x N] fp32 -> out [N x 3072] bf16 = [hi | lo | hi] (transposed, K-major)
__global__ void __launch_bounds__(256) convWT(const float* __restrict__ W,
                                              __nv_bfloat16* __restrict__ out, int N) {
    __shared__ float t[32][33];
    int n0 = blockIdx.x * 32, k0 = blockIdx.y * 32;
    int tx = threadIdx.x & 31, ty = threadIdx.x >> 5;
#pragma unroll
    for (int i = 0; i < 4; i++)
        t[ty + i * 8][tx] = W[(size_t)(k0 + ty + i * 8) * N + n0 + tx];
    __syncthreads();
#pragma unroll
    for (int i = 0; i < 4; i++) {
        int nl = ty + i * 8;
        float v = t[tx][nl];                 // W[k0+tx][n0+nl]
        __nv_bfloat16 hi = __float2bfloat16(v);
        __nv_bfloat16 lo = __float2bfloat16(v - __bfloat162float(hi));
        size_t row = (size_t)(n0 + nl) * K3;
        int k = k0 + tx;
        out[row + k] = hi;
        out[row + 1024 + k] = lo;
        out[row + 2048 + k] = hi;
    }
}

// ---------------- middle: exp(k)^T v partial accumulation + colsum ----------------
__global__ void __launch_bounds__(256) ctx_partial() {
    const int bh = blockIdx.y, chunk = blockIdx.x;
    const float* kp = g_k + (size_t)bh * SEQ * HDIM;
    const float* vp = g_v + (size_t)bh * SEQ * HDIM;
    __shared__ float kt[32][65], vt[32][65], csred[256];
    const int tid = threadIdx.x, e = tid & 63, dg = tid >> 6;
    float acc[16];
#pragma unroll
    for (int j = 0; j < 16; j++) acc[j] = 0.f;
    float csum = 0.f;
    const int n0 = chunk * 128;
    for (int t = 0; t < 4; t++) {
        __syncthreads();
        for (int i = tid; i < 2048; i += 256) {
            int r = i >> 6, c = i & 63;
            size_t g = (size_t)(n0 + t * 32 + r) * 64 + c;
            float ex = __expf(kp[g]);
            kt[r][c] = ex;
            csum += ex;                 // c == tid&63 always
            vt[r][c] = vp[g];
        }
        __syncthreads();
#pragma unroll 4
        for (int r = 0; r < 32; r++) {
            float vv = vt[r][e];
#pragma unroll
            for (int j = 0; j < 16; j++)
                acc[j] = fmaf(kt[r][dg * 16 + j], vv, acc[j]);
        }
    }
#pragma unroll
    for (int j = 0; j < 16; j++)
        atomicAdd(&g_ctx[((size_t)bh * 64 + dg * 16 + j) * 64 + e], acc[j]);
    csred[tid] = csum;
    __syncthreads();
    if (tid < 64)
        atomicAdd(&g_colsum[bh * 64 + tid],
                  csred[tid] + csred[tid + 64] + csred[tid + 128] + csred[tid + 192]);
}

// ---------------- softmax_D(q) @ ctx -> split-bf16 A' for proj GEMM ----------------
__global__ void __launch_bounds__(256) qattend() {
    const int bh = blockIdx.y;
    __shared__ float ctxs[64][65];
    __shared__ float rsum[64];
    __shared__ float pbuf[8][64];
    const int tid = threadIdx.x;
    if (tid < 64) rsum[tid] = 1.f / g_colsum[bh * 64 + tid];
    __syncthreads();
    for (int i = tid; i < 4096; i += 256) {
        int d = i >> 6, ee = i & 63;
        ctxs[d][ee] = g_ctx[((size_t)bh * 64 + d) * 64 + ee] * rsum[d];
    }
    __syncthreads();
    const int warp = tid >> 5, lane = tid & 31;
    const int b = bh >> 4, h = bh & 15;
    for (int rr = 0; rr < 4; rr++) {
        int n = blockIdx.x * 32 + warp * 4 + rr;
        const float* qrow = g_q + ((size_t)bh * SEQ + n) * 64;
        float q0 = qrow[lane], q1 = qrow[lane + 32];
        float mx = fmaxf(q0, q1);
#pragma unroll
        for (int o = 16; o; o >>= 1) mx = fmaxf(mx, __shfl_xor_sync(0xffffffffu, mx, o));
        float e0 = __expf(q0 - mx), e1 = __expf(q1 - mx);
        float s = e0 + e1;
#pragma unroll
        for (int o = 16; o; o >>= 1) s += __shfl_xor_sync(0xffffffffu, s, o);
        float inv = 1.f / s;
        pbuf[warp][lane] = e0 * inv;
        pbuf[warp][lane + 32] = e1 * inv;
        __syncwarp();
        float a0 = 0.f, a1 = 0.f;
#pragma unroll
        for (int d = 0; d < 64; d++) {
            float p = pbuf[warp][d];
            a0 = fmaf(p, ctxs[d][lane], a0);
            a1 = fmaf(p, ctxs[d][lane + 32], a1);
        }
        size_t m = (size_t)b * SEQ + n;
        int k0 = h * 64;
        __nv_bfloat16 h0 = __float2bfloat16(a0);
        __nv_bfloat16 l0 = __float2bfloat16(a0 - __bfloat162float(h0));
        __nv_bfloat16 h1 = __float2bfloat16(a1);
        __nv_bfloat16 l1 = __float2bfloat16(a1 - __bfloat162float(h1));
        __nv_bfloat16* base = g_A + m * K3;
        base[k0 + lane] = h0;         base[k0 + lane + 32] = h1;
        base[1024 + k0 + lane] = h0;  base[1024 + k0 + lane + 32] = h1;
        base[2048 + k0 + lane] = l0;  base[2048 + k0 + lane + 32] = l1;
        __syncwarp();
    }
}

// ---------------------------------------------------------------------------
extern "C" void kernel_launch(void* const* d_in, const int* in_sizes, int n_in,
                              void* d_out, int out_size) {
    const float* x      = (const float*)d_in[0];
    const float* W_qkv  = (const float*)d_in[1];
    const float* b_qkv  = (const float*)d_in[2];
    const float* W_proj = (const float*)d_in[3];
    const float* b_proj = (const float*)d_in[4];
    float* out = (float*)d_out;

    void *pa, *pbq, *pbp, *pctx, *pcs;
    cudaGetSymbolAddress(&pa,  g_A);
    cudaGetSymbolAddress(&pbq, g_Bq);
    cudaGetSymbolAddress(&pbp, g_Bp);
    cudaGetSymbolAddress(&pctx, g_ctx);
    cudaGetSymbolAddress(&pcs,  g_colsum);

    // 1) split conversions
    convA<<<MROWS * CDIM / 1024, 256>>>(x);
    convWT<<<dim3(K3 / 32, CDIM / 32), 256>>>(W_qkv, (__nv_bfloat16*)pbq, K3);
    convWT<<<dim3(CDIM / 32, CDIM / 32), 256>>>(W_proj, (__nv_bfloat16*)pbp, CDIM);
    cudaMemsetAsync(pctx, 0, (size_t)BH * HDIM * HDIM * sizeof(float));
    cudaMemsetAsync(pcs,  0, (size_t)BH * HDIM * sizeof(float));

    // 2) qkv = A' x W_qkv'^T + b  (HMMA), scatter to q/k/v [BH,N,D]
    gemm_hmma<1><<<dim3(K3 / 128, MROWS / 128), 256>>>(
        (const __nv_bfloat16*)pa, (const __nv_bfloat16*)pbq, b_qkv, nullptr, K3);

    // 3) ctx = exp(k)^T v, colsum = sum_n exp(k)
    ctx_partial<<<dim3(SEQ / 128, BH), 256>>>();

    // 4) attn = softmax_D(q) @ (ctx/colsum) -> split-bf16 A'
    qattend<<<dim3(SEQ / 32, BH), 256>>>();

    // 5) out = A' x W_proj'^T + b_proj  (HMMA)
    gemm_hmma<0><<<dim3(CDIM / 128, MROWS / 128), 256>>>(
        (const __nv_bfloat16*)pa, (const __nv_bfloat16*)pbp, b_proj, out, CDIM);
}

// round 4
// speedup vs baseline: 2.5323x; 1.5950x over previous
#include <cuda_runtime.h>
#include <cuda_bf16.h>
#include <cstdint>
#include <math.h>

#define BATCH 4
#define SEQ   4096
#define CDIM  1024
#define HEADS 16
#define HDIM  64
#define MROWS 16384
#define K2    2048          // stored split K: [hi | lo]
#define NKIT  96            // virtual K blocks of 32 (3 segments x 32)
#define BH    64

// ---------------- scratch ----------------
__device__ __nv_bfloat16 g_A[(size_t)MROWS * K2];   // [hi|lo]
__device__ __nv_bfloat16 g_Bq[(size_t)3072 * K2];   // W_qkv split, K-major
__device__ __nv_bfloat16 g_Bp[(size_t)CDIM * K2];   // W_proj split
__device__ float g_q[(size_t)MROWS * CDIM];
__device__ float g_k[(size_t)MROWS * CDIM];
__device__ float g_v[(size_t)MROWS * CDIM];
__device__ float g_ctx[BH * HDIM * HDIM];
__device__ float g_colsum[BH * HDIM];

__device__ __forceinline__ uint32_t smem_u32(const void* p) {
    uint32_t a;
    asm("{ .reg .u64 t; cvta.to.shared.u64 t, %1; cvt.u32.u64 %0, t; }" : "=r"(a) : "l"(p));
    return a;
}
__device__ __forceinline__ void cpa16(uint32_t saddr, const void* g) {
    asm volatile("cp.async.cg.shared.global [%0], [%1], 16;" :: "r"(saddr), "l"(g));
}
#define CPA_COMMIT() asm volatile("cp.async.commit_group;" ::: "memory")

__device__ __forceinline__ void ldm_x4(uint32_t* f, uint32_t addr) {
    asm volatile("ldmatrix.sync.aligned.m8n8.x4.shared.b16 {%0,%1,%2,%3}, [%4];"
        : "=r"(f[0]), "=r"(f[1]), "=r"(f[2]), "=r"(f[3]) : "r"(addr));
}
__device__ __forceinline__ void mma_bf16(float* d, const uint32_t* a, uint32_t b0, uint32_t b1) {
    asm volatile("mma.sync.aligned.m16n8k16.row.col.f32.bf16.bf16.f32 "
        "{%0,%1,%2,%3}, {%4,%5,%6,%7}, {%8,%9}, {%0,%1,%2,%3};"
        : "+f"(d[0]), "+f"(d[1]), "+f"(d[2]), "+f"(d[3])
        : "r"(a[0]), "r"(a[1]), "r"(a[2]), "r"(a[3]), "r"(b0), "r"(b1));
}

// ---------------- HMMA GEMM ----------------
// Virtual K = 3072 (3 segments): seg0 Ahi*Bhi, seg1 Ahi*Blo, seg2 Alo*Bhi.
// BM=BN=128, BK=32, 256 thr, 3-stage cp.async pipeline, 1 sync/iter.
#define SROW   40             // smem row stride (elems): 80B, conflict-free
#define ABYTES 10240          // 128*40*2
#define STGB   20480          // A + B per stage
#define GSMEM  (3 * STGB)     // 61440

__device__ __forceinline__ void load_stage(uint32_t dst,
        const __nv_bfloat16* __restrict__ A, const __nv_bfloat16* __restrict__ B,
        int vi, int bm, int bn, int ldrow, int ldpos) {
    int ka, kb;
    if (vi < 32)      { ka = vi;      kb = vi; }        // hi * hi
    else if (vi < 64) { ka = vi - 32; kb = vi; }        // hi * lo
    else              { ka = vi - 32; kb = vi - 64; }   // lo * hi
    const int kae = ka * 32 + ldpos * 8, kbe = kb * 32 + ldpos * 8;
#pragma unroll
    for (int l = 0; l < 2; l++) {
        int row = ldrow + l * 64;
        uint32_t so = (uint32_t)(row * SROW + ldpos * 8) * 2;
        cpa16(dst + so,          A + (size_t)(bm + row) * K2 + kae);
        cpa16(dst + ABYTES + so, B + (size_t)(bn + row) * K2 + kbe);
    }
    CPA_COMMIT();
}

template<int MODE>
__global__ void __launch_bounds__(256)
gemm_hmma(const __nv_bfloat16* __restrict__ A, const __nv_bfloat16* __restrict__ Bm,
          const float* __restrict__ bias, float* __restrict__ Cout, int Nn)
{
    extern __shared__ __nv_bfloat16 dsm[];
    const uint32_t s0 = smem_u32(dsm);

    const int tid = threadIdx.x, wid = tid >> 5, lane = tid & 31;
    const int bm = blockIdx.y * 128, bn = blockIdx.x * 128;
    const int mbase = (wid >> 2) * 64, nbase = (wid & 3) * 32;
    const int ldrow = tid >> 2, ldpos = tid & 3;

    float acc[4][4][4];
#pragma unroll
    for (int i = 0; i < 4; i++)
#pragma unroll
        for (int j = 0; j < 4; j++)
#pragma unroll
            for (int r = 0; r < 4; r++) acc[i][j][r] = 0.f;

    const int a_row = lane & 15, a_kof = (lane >> 4) * 8;
    const int b_row = (lane & 7) + ((lane >> 4) & 1) * 8;
    const int b_kof = ((lane >> 3) & 1) * 8;

    // prologue: stages 0,1
    load_stage(s0,        A, Bm, 0, bm, bn, ldrow, ldpos);
    load_stage(s0 + STGB, A, Bm, 1, bm, bn, ldrow, ldpos);

    for (int i = 0; i < NKIT; i++) {
        if (i + 2 < NKIT) asm volatile("cp.async.wait_group 1;" ::: "memory");
        else              asm volatile("cp.async.wait_group 0;" ::: "memory");
        __syncthreads();
        if (i + 2 < NKIT)
            load_stage(s0 + ((i + 2) % 3) * STGB, A, Bm, i + 2, bm, bn, ldrow, ldpos);

        const uint32_t sa  = s0 + (i % 3) * STGB;
        const uint32_t sbB = sa + ABYTES;
#pragma unroll
        for (int kc = 0; kc < 2; kc++) {
            uint32_t af[4][4], bfm[2][4];
#pragma unroll
            for (int mt = 0; mt < 4; mt++)
                ldm_x4(af[mt], sa + (uint32_t)((mbase + mt * 16 + a_row) * SROW
                                               + kc * 16 + a_kof) * 2);
#pragma unroll
            for (int np = 0; np < 2; np++)
                ldm_x4(bfm[np], sbB + (uint32_t)((nbase + np * 16 + b_row) * SROW
                                                 + kc * 16 + b_kof) * 2);
#pragma unroll
            for (int mt = 0; mt < 4; mt++)
#pragma unroll
                for (int nt = 0; nt < 4; nt++)
                    mma_bf16(acc[mt][nt], af[mt],
                             bfm[nt >> 1][(nt & 1) * 2], bfm[nt >> 1][(nt & 1) * 2 + 1]);
        }
    }

    // epilogue
    const int r0 = lane >> 2, cpair = (lane & 3) * 2;
#pragma unroll
    for (int mt = 0; mt < 4; mt++) {
#pragma unroll
        for (int nt = 0; nt < 4; nt++) {
            int col = bn + nbase + nt * 8 + cpair;
            float bv0 = bias[col], bv1 = bias[col + 1];
            int m0 = bm + mbase + mt * 16 + r0;
            float2 v0 = make_float2(acc[mt][nt][0] + bv0, acc[mt][nt][1] + bv1);
            float2 v1 = make_float2(acc[mt][nt][2] + bv0, acc[mt][nt][3] + bv1);
            if (MODE == 0) {
                *(float2*)&Cout[(size_t)m0 * Nn + col] = v0;
                *(float2*)&Cout[(size_t)(m0 + 8) * Nn + col] = v1;
            } else {
                int s = col >> 10, rem = col & 1023;
                int h = rem >> 6, dd = rem & 63;
                float* dst = (s == 0) ? g_q : (s == 1) ? g_k : g_v;
                {
                    int b = m0 >> 12, n = m0 & 4095;
                    *(float2*)&dst[(((size_t)(b * HEADS + h) * SEQ + n) << 6) + dd] = v0;
                }
                {
                    int m1 = m0 + 8, b = m1 >> 12, n = m1 & 4095;
                    *(float2*)&dst[(((size_t)(b * HEADS + h) * SEQ + n) << 6) + dd] = v1;
                }
            }
        }
    }
}

// ---------------- conversions ----------------
// x [M x 1024] fp32 -> g_A [M x 2048] = [hi | lo]
__global__ void __launch_bounds__(256) convA(const float* __restrict__ X) {
    int i = blockIdx.x * 256 + threadIdx.x;
    int m = i >> 8;
    int k = (i & 255) << 2;
    float4 v = *(const float4*)(X + (size_t)m * CDIM + k);
    __nv_bfloat16 h0 = __float2bfloat16(v.x), h1 = __float2bfloat16(v.y);
    __nv_bfloat16 h2 = __float2bfloat16(v.z), h3 = __float2bfloat16(v.w);
    __nv_bfloat16 l0 = __float2bfloat16(v.x - __bfloat162float(h0));
    __nv_bfloat16 l1 = __float2bfloat16(v.y - __bfloat162float(h1));
    __nv_bfloat16 l2 = __float2bfloat16(v.z - __bfloat162float(h2));
    __nv_bfloat16 l3 = __float2bfloat16(v.w - __bfloat162float(h3));
    __nv_bfloat16* b = g_A + (size_t)m * K2 + k;
    __nv_bfloat162 H01; H01.x = h0; H01.y = h1;
    __nv_bfloat162 H23; H23.x = h2; H23.y = h3;
    __nv_bfloat162 L01; L01.x = l0; L01.y = l1;
    __nv_bfloat162 L23; L23.x = l2; L23.y = l3;
    ((__nv_bfloat162*)b)[0] = H01;           ((__nv_bfloat162*)b)[1] = H23;
    ((__nv_bfloat162*)(b + 1024))[0] = L01;  ((__nv_bfloat162*)(b + 1024))[1] = L23;
}

// W [1024 K x N] fp32 -> out [N x 2048] = [hi | lo], transposed K-major
__global__ void __launch_bounds__(256) convWT(const float* __restrict__ W,
                                              __nv_bfloat16* __restrict__ out, int N) {
    __shared__ float t[32][33];
    int n0 = blockIdx.x * 32, k0 = blockIdx.y * 32;
    int tx = threadIdx.x & 31, ty = threadIdx.x >> 5;
#pragma unroll
    for (int i = 0; i < 4; i++)
        t[ty + i * 8][tx] = W[(size_t)(k0 + ty + i * 8) * N + n0 + tx];
    __syncthreads();
#pragma unroll
    for (int i = 0; i < 4; i++) {
        int nl = ty + i * 8;
        float v = t[tx][nl];
        __nv_bfloat16 hi = __float2bfloat16(v);
        __nv_bfloat16 lo = __float2bfloat16(v - __bfloat162float(hi));
        size_t row = (size_t)(n0 + nl) * K2;
        int k = k0 + tx;
        out[row + k] = hi;
        out[row + 1024 + k] = lo;
    }
}

// ---------------- middle: exp(k)^T v + colsum, 256-row chunks ----------------
__global__ void __launch_bounds__(256) ctx_partial() {
    const int bh = blockIdx.y, chunk = blockIdx.x;
    const float* kp = g_k + (size_t)bh * SEQ * HDIM;
    const float* vp = g_v + (size_t)bh * SEQ * HDIM;
    __shared__ float kt[32][65], vt[32][65], csred[256];
    const int tid = threadIdx.x, e = tid & 63, dg = tid >> 6;
    float acc[16];
#pragma unroll
    for (int j = 0; j < 16; j++) acc[j] = 0.f;
    float csum = 0.f;
    const int n0 = chunk * 256;
    for (int t = 0; t < 8; t++) {
        __syncthreads();
        for (int i = tid; i < 2048; i += 256) {
            int r = i >> 6, c = i & 63;
            size_t g = (size_t)(n0 + t * 32 + r) * 64 + c;
            float ex = __expf(kp[g]);
            kt[r][c] = ex;
            csum += ex;
            vt[r][c] = vp[g];
        }
        __syncthreads();
#pragma unroll 4
        for (int r = 0; r < 32; r++) {
            float vv = vt[r][e];
#pragma unroll
            for (int j = 0; j < 16; j++)
                acc[j] = fmaf(kt[r][dg * 16 + j], vv, acc[j]);
        }
    }
#pragma unroll
    for (int j = 0; j < 16; j++)
        atomicAdd(&g_ctx[((size_t)bh * 64 + dg * 16 + j) * 64 + e], acc[j]);
    csred[tid] = csum;
    __syncthreads();
    if (tid < 64)
        atomicAdd(&g_colsum[bh * 64 + tid],
                  csred[tid] + csred[tid + 64] + csred[tid + 128] + csred[tid + 192]);
}

// ---------------- softmax_D(q) @ ctx -> split-bf16 g_A ----------------
__global__ void __launch_bounds__(256) qattend() {
    const int bh = blockIdx.y;
    __shared__ float ctxs[64][65];
    __shared__ float rsum[64];
    __shared__ float pbuf[8][64];
    const int tid = threadIdx.x;
    if (tid < 64) rsum[tid] = 1.f / g_colsum[bh * 64 + tid];
    __syncthreads();
    for (int i = tid; i < 4096; i += 256) {
        int d = i >> 6, ee = i & 63;
        ctxs[d][ee] = g_ctx[((size_t)bh * 64 + d) * 64 + ee] * rsum[d];
    }
    __syncthreads();
    const int warp = tid >> 5, lane = tid & 31;
    const int b = bh >> 4, h = bh & 15;
    for (int rr = 0; rr < 4; rr++) {
        int n = blockIdx.x * 32 + warp * 4 + rr;
        const float* qrow = g_q + ((size_t)bh * SEQ + n) * 64;
        float q0 = qrow[lane], q1 = qrow[lane + 32];
        float mx = fmaxf(q0, q1);
#pragma unroll
        for (int o = 16; o; o >>= 1) mx = fmaxf(mx, __shfl_xor_sync(0xffffffffu, mx, o));
        float e0 = __expf(q0 - mx), e1 = __expf(q1 - mx);
        float s = e0 + e1;
#pragma unroll
        for (int o = 16; o; o >>= 1) s += __shfl_xor_sync(0xffffffffu, s, o);
        float inv = 1.f / s;
        pbuf[warp][lane] = e0 * inv;
        pbuf[warp][lane + 32] = e1 * inv;
        __syncwarp();
        float a0 = 0.f, a1 = 0.f;
#pragma unroll
        for (int d = 0; d < 64; d++) {
            float p = pbuf[warp][d];
            a0 = fmaf(p, ctxs[d][lane], a0);
            a1 = fmaf(p, ctxs[d][lane + 32], a1);
        }
        size_t m = (size_t)b * SEQ + n;
        int k0 = h * 64;
        __nv_bfloat16 h0 = __float2bfloat16(a0);
        __nv_bfloat16 l0 = __float2bfloat16(a0 - __bfloat162float(h0));
        __nv_bfloat16 h1 = __float2bfloat16(a1);
        __nv_bfloat16 l1 = __float2bfloat16(a1 - __bfloat162float(h1));
        __nv_bfloat16* base = g_A + m * K2;
        base[k0 + lane] = h0;         base[k0 + lane + 32] = h1;
        base[1024 + k0 + lane] = l0;  base[1024 + k0 + lane + 32] = l1;
        __syncwarp();
    }
}

// ---------------------------------------------------------------------------
extern "C" void kernel_launch(void* const* d_in, const int* in_sizes, int n_in,
                              void* d_out, int out_size) {
    const float* x      = (const float*)d_in[0];
    const float* W_qkv  = (const float*)d_in[1];
    const float* b_qkv  = (const float*)d_in[2];
    const float* W_proj = (const float*)d_in[3];
    const float* b_proj = (const float*)d_in[4];
    float* out = (float*)d_out;

    void *pa, *pbq, *pbp, *pctx, *pcs;
    cudaGetSymbolAddress(&pa,  g_A);
    cudaGetSymbolAddress(&pbq, g_Bq);
    cudaGetSymbolAddress(&pbp, g_Bp);
    cudaGetSymbolAddress(&pctx, g_ctx);
    cudaGetSymbolAddress(&pcs,  g_colsum);

    cudaFuncSetAttribute(gemm_hmma<0>, cudaFuncAttributeMaxDynamicSharedMemorySize, GSMEM);
    cudaFuncSetAttribute(gemm_hmma<1>, cudaFuncAttributeMaxDynamicSharedMemorySize, GSMEM);

    // 1) split conversions
    convA<<<MROWS * CDIM / 1024, 256>>>(x);
    convWT<<<dim3(3072 / 32, CDIM / 32), 256>>>(W_qkv, (__nv_bfloat16*)pbq, 3072);
    convWT<<<dim3(CDIM / 32, CDIM / 32), 256>>>(W_proj, (__nv_bfloat16*)pbp, CDIM);
    cudaMemsetAsync(pctx, 0, (size_t)BH * HDIM * HDIM * sizeof(float));
    cudaMemsetAsync(pcs,  0, (size_t)BH * HDIM * sizeof(float));

    // 2) qkv GEMM (HMMA, 3-stage), scatter to q/k/v
    gemm_hmma<1><<<dim3(3072 / 128, MROWS / 128), 256, GSMEM>>>(
        (const __nv_bfloat16*)pa, (const __nv_bfloat16*)pbq, b_qkv, nullptr, 3072);

    // 3) ctx = exp(k)^T v, colsum
    ctx_partial<<<dim3(SEQ / 256, BH), 256>>>();

    // 4) attn = softmax_D(q) @ (ctx/colsum) -> split-bf16 g_A
    qattend<<<dim3(SEQ / 32, BH), 256>>>();

    // 5) proj GEMM
    gemm_hmma<0><<<dim3(CDIM / 128, MROWS / 128), 256, GSMEM>>>(
        (const __nv_bfloat16*)pa, (const __nv_bfloat16*)pbp, b_proj, out, CDIM);
}

// round 5
// speedup vs baseline: 2.8530x; 1.1266x over previous
#include <cuda_runtime.h>
#include <cuda_bf16.h>
#include <cstdint>
#include <math.h>

#define BATCH 4
#define SEQ   4096
#define CDIM  1024
#define HEADS 16
#define HDIM  64
#define MROWS 16384
#define K2    2048          // stored split K: [hi | lo]
#define NKIT  48            // virtual K blocks of 64 (3 segments x 16)
#define BH    64

// ---------------- scratch ----------------
__device__ __nv_bfloat16 g_A[(size_t)MROWS * K2];   // [hi|lo]
__device__ __nv_bfloat16 g_Bq[(size_t)3072 * K2];   // W_qkv split, K-major
__device__ __nv_bfloat16 g_Bp[(size_t)CDIM * K2];   // W_proj split
__device__ float g_q[(size_t)MROWS * CDIM];
__device__ float g_k[(size_t)MROWS * CDIM];
__device__ float g_v[(size_t)MROWS * CDIM];
__device__ float g_ctx[BH * HDIM * HDIM];
__device__ float g_colsum[BH * HDIM];

__device__ __forceinline__ uint32_t smem_u32(const void* p) {
    uint32_t a;
    asm("{ .reg .u64 t; cvta.to.shared.u64 t, %1; cvt.u32.u64 %0, t; }" : "=r"(a) : "l"(p));
    return a;
}
__device__ __forceinline__ void cpa16(uint32_t saddr, const void* g) {
    asm volatile("cp.async.cg.shared.global [%0], [%1], 16;" :: "r"(saddr), "l"(g));
}
#define CPA_COMMIT() asm volatile("cp.async.commit_group;" ::: "memory")

__device__ __forceinline__ void ldm_x4(uint32_t* f, uint32_t addr) {
    asm volatile("ldmatrix.sync.aligned.m8n8.x4.shared.b16 {%0,%1,%2,%3}, [%4];"
        : "=r"(f[0]), "=r"(f[1]), "=r"(f[2]), "=r"(f[3]) : "r"(addr));
}
__device__ __forceinline__ void mma_bf16(float* d, const uint32_t* a, uint32_t b0, uint32_t b1) {
    asm volatile("mma.sync.aligned.m16n8k16.row.col.f32.bf16.bf16.f32 "
        "{%0,%1,%2,%3}, {%4,%5,%6,%7}, {%8,%9}, {%0,%1,%2,%3};"
        : "+f"(d[0]), "+f"(d[1]), "+f"(d[2]), "+f"(d[3])
        : "r"(a[0]), "r"(a[1]), "r"(a[2]), "r"(a[3]), "r"(b0), "r"(b1));
}

// ---------------- HMMA GEMM ----------------
// Virtual K = 3072 : 48 blocks of 64. seg0 Ahi*Bhi (vi<16), seg1 Ahi*Blo, seg2 Alo*Bhi.
// BM=BN=128, BK=64, 256 thr, warp tile 64x32, 3-stage cp.async, 1 sync/iter.
#define SROW   72              // smem row stride elems (144B) — ldmatrix conflict-free
#define ABYTES (128 * SROW * 2)  // 18432
#define STGB   (2 * ABYTES)      // 36864
#define GSMEM  (3 * STGB)        // 110592

__device__ __forceinline__ void load_stage(uint32_t dst,
        const __nv_bfloat16* __restrict__ A, const __nv_bfloat16* __restrict__ B,
        int vi, int bm, int bn, int tid) {
    int ka, kb;
    if (vi < 16)      { ka = vi;      kb = vi; }        // hi * hi
    else if (vi < 32) { ka = vi - 16; kb = vi; }        // hi * lo
    else              { ka = vi - 16; kb = vi - 32; }   // lo * hi
#pragma unroll
    for (int l = 0; l < 4; l++) {
        int c = tid + l * 256;
        int row = c >> 3, pos = c & 7;
        uint32_t so = (uint32_t)(row * SROW + pos * 8) * 2;
        cpa16(dst + so,          A + (size_t)(bm + row) * K2 + ka * 64 + pos * 8);
        cpa16(dst + ABYTES + so, B + (size_t)(bn + row) * K2 + kb * 64 + pos * 8);
    }
    CPA_COMMIT();
}

template<int MODE>
__global__ void __launch_bounds__(256)
gemm_hmma(const __nv_bfloat16* __restrict__ A, const __nv_bfloat16* __restrict__ Bm,
          const float* __restrict__ bias, float* __restrict__ Cout, int Nn)
{
    extern __shared__ __nv_bfloat16 dsm[];
    const uint32_t s0 = smem_u32(dsm);

    const int tid = threadIdx.x, wid = tid >> 5, lane = tid & 31;
    const int bm = blockIdx.y * 128, bn = blockIdx.x * 128;
    const int mbase = (wid >> 2) * 64, nbase = (wid & 3) * 32;

    float acc[4][4][4];
#pragma unroll
    for (int i = 0; i < 4; i++)
#pragma unroll
        for (int j = 0; j < 4; j++)
#pragma unroll
            for (int r = 0; r < 4; r++) acc[i][j][r] = 0.f;

    const int a_row = lane & 15, a_kof = (lane >> 4) * 8;
    const int b_row = (lane & 7) + ((lane >> 4) & 1) * 8;
    const int b_kof = ((lane >> 3) & 1) * 8;

    load_stage(s0,        A, Bm, 0, bm, bn, tid);
    load_stage(s0 + STGB, A, Bm, 1, bm, bn, tid);

    for (int i = 0; i < NKIT; i++) {
        if (i + 2 < NKIT) asm volatile("cp.async.wait_group 1;" ::: "memory");
        else              asm volatile("cp.async.wait_group 0;" ::: "memory");
        __syncthreads();
        if (i + 2 < NKIT)
            load_stage(s0 + ((i + 2) % 3) * STGB, A, Bm, i + 2, bm, bn, tid);

        const uint32_t sa  = s0 + (i % 3) * STGB;
        const uint32_t sbB = sa + ABYTES;
#pragma unroll
        for (int kc = 0; kc < 4; kc++) {
            uint32_t af[4][4], bfm[2][4];
#pragma unroll
            for (int mt = 0; mt < 4; mt++)
                ldm_x4(af[mt], sa + (uint32_t)((mbase + mt * 16 + a_row) * SROW
                                               + kc * 16 + a_kof) * 2);
#pragma unroll
            for (int np = 0; np < 2; np++)
                ldm_x4(bfm[np], sbB + (uint32_t)((nbase + np * 16 + b_row) * SROW
                                                 + kc * 16 + b_kof) * 2);
#pragma unroll
            for (int mt = 0; mt < 4; mt++)
#pragma unroll
                for (int nt = 0; nt < 4; nt++)
                    mma_bf16(acc[mt][nt], af[mt],
                             bfm[nt >> 1][(nt & 1) * 2], bfm[nt >> 1][(nt & 1) * 2 + 1]);
        }
    }

    // epilogue
    const int r0 = lane >> 2, cpair = (lane & 3) * 2;
#pragma unroll
    for (int mt = 0; mt < 4; mt++) {
#pragma unroll
        for (int nt = 0; nt < 4; nt++) {
            int col = bn + nbase + nt * 8 + cpair;
            float bv0 = bias[col], bv1 = bias[col + 1];
            int m0 = bm + mbase + mt * 16 + r0;
            float2 v0 = make_float2(acc[mt][nt][0] + bv0, acc[mt][nt][1] + bv1);
            float2 v1 = make_float2(acc[mt][nt][2] + bv0, acc[mt][nt][3] + bv1);
            if (MODE == 0) {
                *(float2*)&Cout[(size_t)m0 * Nn + col] = v0;
                *(float2*)&Cout[(size_t)(m0 + 8) * Nn + col] = v1;
            } else {
                int s = col >> 10, rem = col & 1023;
                int h = rem >> 6, dd = rem & 63;
                float* dst = (s == 0) ? g_q : (s == 1) ? g_k : g_v;
                {
                    int b = m0 >> 12, n = m0 & 4095;
                    *(float2*)&dst[(((size_t)(b * HEADS + h) * SEQ + n) << 6) + dd] = v0;
                }
                {
                    int m1 = m0 + 8, b = m1 >> 12, n = m1 & 4095;
                    *(float2*)&dst[(((size_t)(b * HEADS + h) * SEQ + n) << 6) + dd] = v1;
                }
            }
        }
    }
}

// ---------------- conversions ----------------
__global__ void __launch_bounds__(256) convA(const float* __restrict__ X) {
    int i = blockIdx.x * 256 + threadIdx.x;
    int m = i >> 8;
    int k = (i & 255) << 2;
    float4 v = *(const float4*)(X + (size_t)m * CDIM + k);
    __nv_bfloat16 h0 = __float2bfloat16(v.x), h1 = __float2bfloat16(v.y);
    __nv_bfloat16 h2 = __float2bfloat16(v.z), h3 = __float2bfloat16(v.w);
    __nv_bfloat16 l0 = __float2bfloat16(v.x - __bfloat162float(h0));
    __nv_bfloat16 l1 = __float2bfloat16(v.y - __bfloat162float(h1));
    __nv_bfloat16 l2 = __float2bfloat16(v.z - __bfloat162float(h2));
    __nv_bfloat16 l3 = __float2bfloat16(v.w - __bfloat162float(h3));
    __nv_bfloat16* b = g_A + (size_t)m * K2 + k;
    __nv_bfloat162 H01; H01.x = h0; H01.y = h1;
    __nv_bfloat162 H23; H23.x = h2; H23.y = h3;
    __nv_bfloat162 L01; L01.x = l0; L01.y = l1;
    __nv_bfloat162 L23; L23.x = l2; L23.y = l3;
    ((__nv_bfloat162*)b)[0] = H01;           ((__nv_bfloat162*)b)[1] = H23;
    ((__nv_bfloat162*)(b + 1024))[0] = L01;  ((__nv_bfloat162*)(b + 1024))[1] = L23;
}

__global__ void __launch_bounds__(256) convWT(const float* __restrict__ W,
                                              __nv_bfloat16* __restrict__ out, int N) {
    __shared__ float t[32][33];
    int n0 = blockIdx.x * 32, k0 = blockIdx.y * 32;
    int tx = threadIdx.x & 31, ty = threadIdx.x >> 5;
#pragma unroll
    for (int i = 0; i < 4; i++)
        t[ty + i * 8][tx] = W[(size_t)(k0 + ty + i * 8) * N + n0 + tx];
    __syncthreads();
#pragma unroll
    for (int i = 0; i < 4; i++) {
        int nl = ty + i * 8;
        float v = t[tx][nl];
        __nv_bfloat16 hi = __float2bfloat16(v);
        __nv_bfloat16 lo = __float2bfloat16(v - __bfloat162float(hi));
        size_t row = (size_t)(n0 + nl) * K2;
        int k = k0 + tx;
        out[row + k] = hi;
        out[row + 1024 + k] = lo;
    }
}

// ---------------- middle: exp(k)^T v + colsum ----------------
__global__ void __launch_bounds__(256) ctx_partial() {
    const int bh = blockIdx.y, chunk = blockIdx.x;
    const float* kp = g_k + (size_t)bh * SEQ * HDIM;
    const float* vp = g_v + (size_t)bh * SEQ * HDIM;
    __shared__ float kt[32][65], vt[32][65], csred[256];
    const int tid = threadIdx.x, e = tid & 63, dg = tid >> 6;
    float acc[16];
#pragma unroll
    for (int j = 0; j < 16; j++) acc[j] = 0.f;
    float csum = 0.f;
    const int n0 = chunk * 256;
    for (int t = 0; t < 8; t++) {
        __syncthreads();
        for (int i = tid; i < 2048; i += 256) {
            int r = i >> 6, c = i & 63;
            size_t g = (size_t)(n0 + t * 32 + r) * 64 + c;
            float ex = __expf(kp[g]);
            kt[r][c] = ex;
            csum += ex;
            vt[r][c] = vp[g];
        }
        __syncthreads();
#pragma unroll 4
        for (int r = 0; r < 32; r++) {
            float vv = vt[r][e];
#pragma unroll
            for (int j = 0; j < 16; j++)
                acc[j] = fmaf(kt[r][dg * 16 + j], vv, acc[j]);
        }
    }
#pragma unroll
    for (int j = 0; j < 16; j++)
        atomicAdd(&g_ctx[((size_t)bh * 64 + dg * 16 + j) * 64 + e], acc[j]);
    csred[tid] = csum;
    __syncthreads();
    if (tid < 64)
        atomicAdd(&g_colsum[bh * 64 + tid],
                  csred[tid] + csred[tid + 64] + csred[tid + 128] + csred[tid + 192]);
}

// ---------------- softmax_D(q) @ ctx -> split-bf16 g_A ----------------
__global__ void __launch_bounds__(256) qattend() {
    const int bh = blockIdx.y;
    __shared__ float ctxs[64][65];
    __shared__ float rsum[64];
    __shared__ float pbuf[8][64];
    const int tid = threadIdx.x;
    if (tid < 64) rsum[tid] = 1.f / g_colsum[bh * 64 + tid];
    __syncthreads();
    for (int i = tid; i < 4096; i += 256) {
        int d = i >> 6, ee = i & 63;
        ctxs[d][ee] = g_ctx[((size_t)bh * 64 + d) * 64 + ee] * rsum[d];
    }
    __syncthreads();
    const int warp = tid >> 5, lane = tid & 31;
    const int b = bh >> 4, h = bh & 15;
    for (int rr = 0; rr < 4; rr++) {
        int n = blockIdx.x * 32 + warp * 4 + rr;
        const float* qrow = g_q + ((size_t)bh * SEQ + n) * 64;
        float q0 = qrow[lane], q1 = qrow[lane + 32];
        float mx = fmaxf(q0, q1);
#pragma unroll
        for (int o = 16; o; o >>= 1) mx = fmaxf(mx, __shfl_xor_sync(0xffffffffu, mx, o));
        float e0 = __expf(q0 - mx), e1 = __expf(q1 - mx);
        float s = e0 + e1;
#pragma unroll
        for (int o = 16; o; o >>= 1) s += __shfl_xor_sync(0xffffffffu, s, o);
        float inv = 1.f / s;
        pbuf[warp][lane] = e0 * inv;
        pbuf[warp][lane + 32] = e1 * inv;
        __syncwarp();
        float a0 = 0.f, a1 = 0.f;
#pragma unroll
        for (int d = 0; d < 64; d++) {
            float p = pbuf[warp][d];
            a0 = fmaf(p, ctxs[d][lane], a0);
            a1 = fmaf(p, ctxs[d][lane + 32], a1);
        }
        size_t m = (size_t)b * SEQ + n;
        int k0 = h * 64;
        __nv_bfloat16 h0 = __float2bfloat16(a0);
        __nv_bfloat16 l0 = __float2bfloat16(a0 - __bfloat162float(h0));
        __nv_bfloat16 h1 = __float2bfloat16(a1);
        __nv_bfloat16 l1 = __float2bfloat16(a1 - __bfloat162float(h1));
        __nv_bfloat16* base = g_A + m * K2;
        base[k0 + lane] = h0;         base[k0 + lane + 32] = h1;
        base[1024 + k0 + lane] = l0;  base[1024 + k0 + lane + 32] = l1;
        __syncwarp();
    }
}

// ---------------------------------------------------------------------------
extern "C" void kernel_launch(void* const* d_in, const int* in_sizes, int n_in,
                              void* d_out, int out_size) {
    const float* x      = (const float*)d_in[0];
    const float* W_qkv  = (const float*)d_in[1];
    const float* b_qkv  = (const float*)d_in[2];
    const float* W_proj = (const float*)d_in[3];
    const float* b_proj = (const float*)d_in[4];
    float* out = (float*)d_out;

    void *pa, *pbq, *pbp, *pctx, *pcs;
    cudaGetSymbolAddress(&pa,  g_A);
    cudaGetSymbolAddress(&pbq, g_Bq);
    cudaGetSymbolAddress(&pbp, g_Bp);
    cudaGetSymbolAddress(&pctx, g_ctx);
    cudaGetSymbolAddress(&pcs,  g_colsum);

    cudaFuncSetAttribute(gemm_hmma<0>, cudaFuncAttributeMaxDynamicSharedMemorySize, GSMEM);
    cudaFuncSetAttribute(gemm_hmma<1>, cudaFuncAttributeMaxDynamicSharedMemorySize, GSMEM);

    convA<<<MROWS * CDIM / 1024, 256>>>(x);
    convWT<<<dim3(3072 / 32, CDIM / 32), 256>>>(W_qkv, (__nv_bfloat16*)pbq, 3072);
    convWT<<<dim3(CDIM / 32, CDIM / 32), 256>>>(W_proj, (__nv_bfloat16*)pbp, CDIM);
    cudaMemsetAsync(pctx, 0, (size_t)BH * HDIM * HDIM * sizeof(float));
    cudaMemsetAsync(pcs,  0, (size_t)BH * HDIM * sizeof(float));

    gemm_hmma<1><<<dim3(3072 / 128, MROWS / 128), 256, GSMEM>>>(
        (const __nv_bfloat16*)pa, (const __nv_bfloat16*)pbq, b_qkv, nullptr, 3072);

    ctx_partial<<<dim3(SEQ / 256, BH), 256>>>();
    qattend<<<dim3(SEQ / 32, BH), 256>>>();

    gemm_hmma<0><<<dim3(CDIM / 128, MROWS / 128), 256, GSMEM>>>(
        (const __nv_bfloat16*)pa, (const __nv_bfloat16*)pbp, b_proj, out, CDIM);
}